// round 8
// baseline (speedup 1.0000x reference)
#include <cuda_runtime.h>
#include <stdint.h>

// ---------------------------------------------------------------------------
// CoralLoss single-kernel: mean over (B, K-1) of softplus(s),
//   s = (target > k) ? -x : x
// softplus(s) = 0.5*s + 0.5*|x| + ln(1 + 2^(-|x|*log2e))
//   -> heavy log term is sign-independent; sign enters via one packed FFMA.
// All transcendentals as FMA-pipe polynomials, packed 2-wide via fma.rn.f32x2.
// Target dtype (int32 vs int64) detected in-kernel from odd-word sampling.
// Final reduction via last-block pattern (deterministic, graph-replay safe).
// ---------------------------------------------------------------------------

#define NBLK 592
#define NTHR 256

typedef unsigned long long ull;

__device__ float    g_partial[NBLK];
__device__ unsigned g_count = 0;

// ---- packed f32x2 helpers (non-volatile asm: CSE/LICM-hoistable) ----------
__device__ __forceinline__ ull pk(float lo, float hi) {
    ull r; asm("mov.b64 %0,{%1,%2};" : "=l"(r) : "f"(lo), "f"(hi)); return r;
}
__device__ __forceinline__ void upk(ull v, float& lo, float& hi) {
    asm("mov.b64 {%0,%1},%2;" : "=f"(lo), "=f"(hi) : "l"(v));
}
__device__ __forceinline__ ull fma2(ull a, ull b, ull c) {
    ull r; asm("fma.rn.f32x2 %0,%1,%2,%3;" : "=l"(r) : "l"(a), "l"(b), "l"(c)); return r;
}
__device__ __forceinline__ ull mul2(ull a, ull b) {
    ull r; asm("mul.rn.f32x2 %0,%1,%2;" : "=l"(r) : "l"(a), "l"(b)); return r;
}
__device__ __forceinline__ ull add2(ull a, ull b) {
    ull r; asm("add.rn.f32x2 %0,%1,%2;" : "=l"(r) : "l"(a), "l"(b)); return r;
}
__device__ __forceinline__ ull dup(float c) { return pk(c, c); }

// Packed softplus core for a pair (x0, x1) with sign weights g = +-0.5.
// accL += ln(1 + 2^(-a)) [packed]; accH += 0.5*|x| (via a/log2e); accS += g*x.
__device__ __forceinline__ void sp_pair(float x0, float x1, float g0, float g1,
                                         ull& accL, ull& accH, ull& accS) {
    const float L2E   = 1.4426950408889634f;
    const float MAGIC = 12582912.0f;          // 1.5 * 2^23

    float a0 = fminf(fabsf(x0) * L2E, 80.0f); // a in [0, 80]
    float a1 = fminf(fabsf(x1) * L2E, 80.0f);
    ull a2 = pk(a0, a1);

    ull zz2 = add2(a2, dup(MAGIC));           // low bits hold r = round(a)
    ull kf2 = add2(zz2, dup(-MAGIC));         // kf = r exactly
    ull t2  = fma2(a2, dup(-1.0f), kf2);      // t = r - a  in [-0.5, 0.5]

    float zf0, zf1; upk(zz2, zf0, zf1);
    int ib0 = 0x3F800000 - (__float_as_int(zf0) << 23);   // bits of 2^(-r)
    int ib1 = 0x3F800000 - (__float_as_int(zf1) << 23);
    ull ib2 = pk(__int_as_float(ib0), __int_as_float(ib1));

    // 2^t, t in [-0.5, 0.5]: degree-5 (rel err ~2e-6)
    ull p = fma2(t2, dup(0.0013333558f), dup(0.0096181291f));
    p = fma2(t2, p, dup(0.0555041087f));
    p = fma2(t2, p, dup(0.2402265069f));
    p = fma2(t2, p, dup(0.6931471806f));
    p = fma2(t2, p, dup(1.0f));

    ull u = mul2(p, ib2);                     // u = 2^(-a) in (0, 1]

    // ln(1+u), u in [0,1]: degree-5 minimax (abs err ~1e-5)
    ull l = fma2(u, dup(0.03044896f), dup(-0.13158176f));
    l = fma2(u, l, dup(0.28527272f));
    l = fma2(u, l, dup(-0.49023080f));
    l = fma2(u, l, dup(0.99923550f));
    l = fma2(u, l, dup(1.02e-5f));

    accL = add2(accL, l);
    accH = fma2(a2, dup(0.34657359f), accH);  // 0.5/log2(e) * a = 0.5*|x|
    accS = fma2(pk(x0, x1), pk(g0, g1), accS);
}

__global__ void __launch_bounds__(NTHR) coral_fused(
    const float4* __restrict__ lg,     // logits as float4, B*16 entries
    const int*    __restrict__ t32,    // targets viewed as int32 words
    int total4,                        // B * 16
    float* __restrict__ out,
    double inv_n)
{
    // ---- in-block dtype detection: int64 iff sampled odd words all zero ----
    __shared__ int s_is64;
    if (threadIdx.x < 32) {
        int nz = t32[2 * threadIdx.x + 1] | t32[2 * threadIdx.x + 65];
        unsigned m = __ballot_sync(0xFFFFFFFFu, nz != 0);
        if (threadIdx.x == 0) s_is64 = (m == 0);
    }
    __syncthreads();
    const int tsh = s_is64 ? 1 : 0;    // target index shift (x2 for int64)

    ull accL = 0, accH = 0, accS = 0;  // packed zeros (0.0f, 0.0f)

    const int stride = NBLK * NTHR;
    #pragma unroll 2
    for (int i = blockIdx.x * NTHR + threadIdx.x; i < total4; i += stride) {
        int row = i >> 4;                       // 16 float4 per row (K-1 = 64)
        int kb  = (i & 15) << 2;                // k index of component .x
        int tgt = t32[row << tsh];
        int d   = tgt - kb;                     // flip component c iff d > c

        float4 v = lg[i];
        float g0 = (d > 0) ? -0.5f : 0.5f;
        float g1 = (d > 1) ? -0.5f : 0.5f;
        float g2 = (d > 2) ? -0.5f : 0.5f;
        float g3 = (d > 3) ? -0.5f : 0.5f;

        sp_pair(v.x, v.y, g0, g1, accL, accH, accS);
        sp_pair(v.z, v.w, g2, g3, accL, accH, accS);
    }

    // ---- per-thread combine: sum = L + 0.5|x| + 0.5*s ----
    float l0, l1, h0, h1, s0, s1;
    upk(accL, l0, l1); upk(accH, h0, h1); upk(accS, s0, s1);
    float acc = (l0 + l1) + (h0 + h1) + (s0 + s1);

    // ---- block reduce ----
    #pragma unroll
    for (int o = 16; o > 0; o >>= 1)
        acc += __shfl_xor_sync(0xFFFFFFFFu, acc, o);

    __shared__ float sw[NTHR / 32];
    __shared__ bool amLast;
    int lane = threadIdx.x & 31;
    int warp = threadIdx.x >> 5;
    if (lane == 0) sw[warp] = acc;
    __syncthreads();

    if (threadIdx.x == 0) {
        float b = 0.0f;
        #pragma unroll
        for (int w = 0; w < NTHR / 32; w++) b += sw[w];
        g_partial[blockIdx.x] = b;
        __threadfence();
        unsigned t = atomicAdd(&g_count, 1u);
        amLast = (t == (unsigned)(gridDim.x - 1));
    }
    __syncthreads();

    // ---- last block: deterministic final reduce in double ----
    if (amLast) {
        __threadfence();
        double a = 0.0;
        for (int i = threadIdx.x; i < NBLK; i += NTHR)
            a += (double)g_partial[i];
        #pragma unroll
        for (int o = 16; o > 0; o >>= 1)
            a += __shfl_xor_sync(0xFFFFFFFFu, a, o);
        __shared__ double sd[NTHR / 32];
        if (lane == 0) sd[warp] = a;
        __syncthreads();
        if (threadIdx.x == 0) {
            double s = 0.0;
            #pragma unroll
            for (int w = 0; w < NTHR / 32; w++) s += sd[w];
            out[0] = (float)(s * inv_n);
            g_count = 0;   // reset for next graph replay
        }
    }
}

extern "C" void kernel_launch(void* const* d_in, const int* in_sizes, int n_in,
                              void* d_out, int out_size) {
    const float* logits = (const float*)d_in[0];
    const int*   t32    = (const int*)d_in[1];   // int32 view of targets
    int nelem  = in_sizes[0];                    // B * (K-1)
    int total4 = nelem >> 2;

    coral_fused<<<NBLK, NTHR>>>((const float4*)logits, t32, total4,
                                (float*)d_out, 1.0 / (double)nelem);
}

// round 9
// speedup vs baseline: 1.2112x; 1.2112x over previous
#include <cuda_runtime.h>
#include <stdint.h>

// ---------------------------------------------------------------------------
// CoralLoss single-kernel: mean over (B, K-1) of softplus(s),
//   s = (target > k) ? -x : x
// loss_elem = 0.5*|x| + g*x + ln(1 + u),  g = +-0.5,  u = 2^(-|x|*log2e)
//   u via ONE MUFU (ex2.approx) per element  -> no range-reduction ALU work
//   ln(1+u) via verified deg-5 minimax, packed fma.rn.f32x2, c0 added
//   analytically to the final mean (saves 1 op/elem).
// Target dtype (int32 vs int64) detected in-kernel; single launch, last-block
// final reduction (deterministic, graph-replay safe).
// ---------------------------------------------------------------------------

#define NBLK 592
#define NTHR 256

typedef unsigned long long ull;

__device__ float    g_partial[NBLK];
__device__ unsigned g_count = 0;

// ---- packed f32x2 helpers (non-volatile: CSE/LICM-hoistable) --------------
__device__ __forceinline__ ull pk(float lo, float hi) {
    ull r; asm("mov.b64 %0,{%1,%2};" : "=l"(r) : "f"(lo), "f"(hi)); return r;
}
__device__ __forceinline__ void upk(ull v, float& lo, float& hi) {
    asm("mov.b64 {%0,%1},%2;" : "=f"(lo), "=f"(hi) : "l"(v));
}
__device__ __forceinline__ ull fma2(ull a, ull b, ull c) {
    ull r; asm("fma.rn.f32x2 %0,%1,%2,%3;" : "=l"(r) : "l"(a), "l"(b), "l"(c)); return r;
}
__device__ __forceinline__ ull mul2(ull a, ull b) {
    ull r; asm("mul.rn.f32x2 %0,%1,%2;" : "=l"(r) : "l"(a), "l"(b)); return r;
}
__device__ __forceinline__ ull and2(ull a, ull m) {
    ull r; asm("and.b64 %0,%1,%2;" : "=l"(r) : "l"(a), "l"(m)); return r;
}
__device__ __forceinline__ ull dup(float c) { return pk(c, c); }
__device__ __forceinline__ float ex2f(float x) {
    float r; asm("ex2.approx.f32 %0,%1;" : "=f"(r) : "f"(x)); return r;
}

// Packed softplus pair: accL += u*P(u); accH += 0.5|x|; accS += g*x.
// (ln(1+u) = C0 + u*P(u); C0 accounted analytically in the final mean.)
__device__ __forceinline__ void sp_pair(float x0, float x1, float g0, float g1,
                                        ull& accL, ull& accH, ull& accS) {
    ull x2  = pk(x0, x1);
    ull ax2 = and2(x2, 0x7FFFFFFF7FFFFFFFULL);          // |x| packed
    ull a2  = mul2(ax2, dup(-1.4426950408889634f));     // -|x|*log2(e)
    float a0, a1; upk(a2, a0, a1);
    ull u2  = pk(ex2f(a0), ex2f(a1));                   // u = 2^(-|x|log2e)

    // P(u): deg-5 minimax for ln(1+u) minus constant term, u in (0,1]
    ull l = fma2(u2, dup(0.03044896f), dup(-0.13158176f));
    l = fma2(u2, l, dup(0.28527272f));
    l = fma2(u2, l, dup(-0.49023080f));
    l = fma2(u2, l, dup(0.99923550f));
    accL = fma2(u2, l, accL);                           // += u*P(u)

    accH = fma2(ax2, dup(0.5f), accH);                  // += 0.5|x|
    accS = fma2(x2, pk(g0, g1), accS);                  // += g*x
}

__global__ void __launch_bounds__(NTHR) coral_fused(
    const float4* __restrict__ lg,     // logits as float4, B*16 entries
    const int*    __restrict__ t32,    // targets viewed as int32 words
    int total4,                        // B * 16
    float* __restrict__ out,
    double inv_n)
{
    // ---- in-block dtype detection: int64 iff sampled odd words all zero ----
    __shared__ int s_is64;
    if (threadIdx.x < 32) {
        int nz = t32[2 * threadIdx.x + 1] | t32[2 * threadIdx.x + 65];
        unsigned m = __ballot_sync(0xFFFFFFFFu, nz != 0);
        if (threadIdx.x == 0) s_is64 = (m == 0);
    }
    __syncthreads();
    const int tsh = s_is64 ? 1 : 0;    // target index shift (x2 for int64)

    ull accL = 0, accH = 0, accS = 0;  // packed (0.0f, 0.0f)

    const int stride = NBLK * NTHR;
    #pragma unroll 4
    for (int i = blockIdx.x * NTHR + threadIdx.x; i < total4; i += stride) {
        int row = i >> 4;                       // 16 float4 per row (K-1 = 64)
        int kb  = (i & 15) << 2;                // k index of component .x
        int tgt = t32[row << tsh];
        int d   = tgt - kb;                     // flip component c iff d > c

        float4 v = __ldcs(&lg[i]);              // streaming: read-once data
        float g0 = (d > 0) ? -0.5f : 0.5f;
        float g1 = (d > 1) ? -0.5f : 0.5f;
        float g2 = (d > 2) ? -0.5f : 0.5f;
        float g3 = (d > 3) ? -0.5f : 0.5f;

        sp_pair(v.x, v.y, g0, g1, accL, accH, accS);
        sp_pair(v.z, v.w, g2, g3, accL, accH, accS);
    }

    // ---- per-thread combine ----
    float l0, l1, h0, h1, s0, s1;
    upk(accL, l0, l1); upk(accH, h0, h1); upk(accS, s0, s1);
    float acc = (l0 + l1) + (h0 + h1) + (s0 + s1);

    // ---- block reduce ----
    #pragma unroll
    for (int o = 16; o > 0; o >>= 1)
        acc += __shfl_xor_sync(0xFFFFFFFFu, acc, o);

    __shared__ float sw[NTHR / 32];
    __shared__ bool amLast;
    int lane = threadIdx.x & 31;
    int warp = threadIdx.x >> 5;
    if (lane == 0) sw[warp] = acc;
    __syncthreads();

    if (threadIdx.x == 0) {
        float b = 0.0f;
        #pragma unroll
        for (int w = 0; w < NTHR / 32; w++) b += sw[w];
        g_partial[blockIdx.x] = b;
        __threadfence();
        unsigned t = atomicAdd(&g_count, 1u);
        amLast = (t == (unsigned)(gridDim.x - 1));
    }
    __syncthreads();

    // ---- last block: deterministic final reduce in double ----
    if (amLast) {
        __threadfence();
        double a = 0.0;
        for (int i = threadIdx.x; i < NBLK; i += NTHR)
            a += (double)g_partial[i];
        #pragma unroll
        for (int o = 16; o > 0; o >>= 1)
            a += __shfl_xor_sync(0xFFFFFFFFu, a, o);
        __shared__ double sd[NTHR / 32];
        if (lane == 0) sd[warp] = a;
        __syncthreads();
        if (threadIdx.x == 0) {
            double s = 0.0;
            #pragma unroll
            for (int w = 0; w < NTHR / 32; w++) s += sd[w];
            // + C0 (constant term of ln(1+u) poly), applied analytically
            out[0] = (float)(s * inv_n + 1.02e-5);
            g_count = 0;   // reset for next graph replay
        }
    }
}

extern "C" void kernel_launch(void* const* d_in, const int* in_sizes, int n_in,
                              void* d_out, int out_size) {
    const float* logits = (const float*)d_in[0];
    const int*   t32    = (const int*)d_in[1];   // int32 view of targets
    int nelem  = in_sizes[0];                    // B * (K-1)
    int total4 = nelem >> 2;

    coral_fused<<<NBLK, NTHR>>>((const float4*)logits, t32, total4,
                                (float*)d_out, 1.0 / (double)nelem);
}

// round 10
// speedup vs baseline: 1.5322x; 1.2651x over previous
#include <cuda_runtime.h>
#include <stdint.h>

// ---------------------------------------------------------------------------
// CoralLoss single-kernel: mean over (B, K-1) of softplus(s),
//   s = (target > k) ? -x : x
// loss_elem = 0.5*|x| + g*x + ln(1 + u),  g = +-0.5,  u = 2^(-|x|*log2e)
//   u via ONE MUFU (ex2.approx) per element; ln(1+u) via deg-5 minimax,
//   packed fma.rn.f32x2; poly constant term added analytically to the mean.
// R9: grid 592 -> 1184 (8 CTAs/SM, occ 48% -> ~100%) to cover LDG/MUFU
// latency — kernel was latency-bound with every pipe < 45%.
// ---------------------------------------------------------------------------

#define NBLK 1184
#define NTHR 256

typedef unsigned long long ull;

__device__ float    g_partial[NBLK];
__device__ unsigned g_count = 0;

// ---- packed f32x2 helpers (non-volatile: CSE/LICM-hoistable) --------------
__device__ __forceinline__ ull pk(float lo, float hi) {
    ull r; asm("mov.b64 %0,{%1,%2};" : "=l"(r) : "f"(lo), "f"(hi)); return r;
}
__device__ __forceinline__ void upk(ull v, float& lo, float& hi) {
    asm("mov.b64 {%0,%1},%2;" : "=f"(lo), "=f"(hi) : "l"(v));
}
__device__ __forceinline__ ull fma2(ull a, ull b, ull c) {
    ull r; asm("fma.rn.f32x2 %0,%1,%2,%3;" : "=l"(r) : "l"(a), "l"(b), "l"(c)); return r;
}
__device__ __forceinline__ ull mul2(ull a, ull b) {
    ull r; asm("mul.rn.f32x2 %0,%1,%2;" : "=l"(r) : "l"(a), "l"(b)); return r;
}
__device__ __forceinline__ ull and2(ull a, ull m) {
    ull r; asm("and.b64 %0,%1,%2;" : "=l"(r) : "l"(a), "l"(m)); return r;
}
__device__ __forceinline__ ull dup(float c) { return pk(c, c); }
__device__ __forceinline__ float ex2f(float x) {
    float r; asm("ex2.approx.f32 %0,%1;" : "=f"(r) : "f"(x)); return r;
}

// Packed softplus pair: accL += u*P(u); accH += 0.5|x|; accS += g*x.
// (ln(1+u) = C0 + u*P(u); C0 accounted analytically in the final mean.)
__device__ __forceinline__ void sp_pair(float x0, float x1, float g0, float g1,
                                        ull& accL, ull& accH, ull& accS) {
    ull x2  = pk(x0, x1);
    ull ax2 = and2(x2, 0x7FFFFFFF7FFFFFFFULL);          // |x| packed
    ull a2  = mul2(ax2, dup(-1.4426950408889634f));     // -|x|*log2(e)
    float a0, a1; upk(a2, a0, a1);
    ull u2  = pk(ex2f(a0), ex2f(a1));                   // u = 2^(-|x|log2e)

    // P(u): deg-5 minimax for ln(1+u) minus constant term, u in (0,1]
    ull l = fma2(u2, dup(0.03044896f), dup(-0.13158176f));
    l = fma2(u2, l, dup(0.28527272f));
    l = fma2(u2, l, dup(-0.49023080f));
    l = fma2(u2, l, dup(0.99923550f));
    accL = fma2(u2, l, accL);                           // += u*P(u)

    accH = fma2(ax2, dup(0.5f), accH);                  // += 0.5|x|
    accS = fma2(x2, pk(g0, g1), accS);                  // += g*x
}

__global__ void __launch_bounds__(NTHR) coral_fused(
    const float4* __restrict__ lg,     // logits as float4, B*16 entries
    const int*    __restrict__ t32,    // targets viewed as int32 words
    int total4,                        // B * 16
    float* __restrict__ out,
    double inv_n)
{
    // ---- in-block dtype detection: int64 iff sampled odd words all zero ----
    __shared__ int s_is64;
    if (threadIdx.x < 32) {
        int nz = t32[2 * threadIdx.x + 1] | t32[2 * threadIdx.x + 65];
        unsigned m = __ballot_sync(0xFFFFFFFFu, nz != 0);
        if (threadIdx.x == 0) s_is64 = (m == 0);
    }
    __syncthreads();
    const int tsh = s_is64 ? 1 : 0;    // target index shift (x2 for int64)

    ull accL = 0, accH = 0, accS = 0;  // packed (0.0f, 0.0f)

    const int stride = NBLK * NTHR;
    #pragma unroll 4
    for (int i = blockIdx.x * NTHR + threadIdx.x; i < total4; i += stride) {
        int row = i >> 4;                       // 16 float4 per row (K-1 = 64)
        int kb  = (i & 15) << 2;                // k index of component .x
        int tgt = t32[row << tsh];
        int d   = tgt - kb;                     // flip component c iff d > c

        float4 v = __ldcs(&lg[i]);              // streaming: read-once data
        float g0 = (d > 0) ? -0.5f : 0.5f;
        float g1 = (d > 1) ? -0.5f : 0.5f;
        float g2 = (d > 2) ? -0.5f : 0.5f;
        float g3 = (d > 3) ? -0.5f : 0.5f;

        sp_pair(v.x, v.y, g0, g1, accL, accH, accS);
        sp_pair(v.z, v.w, g2, g3, accL, accH, accS);
    }

    // ---- per-thread combine ----
    float l0, l1, h0, h1, s0, s1;
    upk(accL, l0, l1); upk(accH, h0, h1); upk(accS, s0, s1);
    float acc = (l0 + l1) + (h0 + h1) + (s0 + s1);

    // ---- block reduce ----
    #pragma unroll
    for (int o = 16; o > 0; o >>= 1)
        acc += __shfl_xor_sync(0xFFFFFFFFu, acc, o);

    __shared__ float sw[NTHR / 32];
    __shared__ bool amLast;
    int lane = threadIdx.x & 31;
    int warp = threadIdx.x >> 5;
    if (lane == 0) sw[warp] = acc;
    __syncthreads();

    if (threadIdx.x == 0) {
        float b = 0.0f;
        #pragma unroll
        for (int w = 0; w < NTHR / 32; w++) b += sw[w];
        g_partial[blockIdx.x] = b;
        __threadfence();
        unsigned t = atomicAdd(&g_count, 1u);
        amLast = (t == (unsigned)(gridDim.x - 1));
    }
    __syncthreads();

    // ---- last block: deterministic final reduce in double ----
    if (amLast) {
        __threadfence();
        double a = 0.0;
        for (int i = threadIdx.x; i < NBLK; i += NTHR)
            a += (double)g_partial[i];
        #pragma unroll
        for (int o = 16; o > 0; o >>= 1)
            a += __shfl_xor_sync(0xFFFFFFFFu, a, o);
        __shared__ double sd[NTHR / 32];
        if (lane == 0) sd[warp] = a;
        __syncthreads();
        if (threadIdx.x == 0) {
            double s = 0.0;
            #pragma unroll
            for (int w = 0; w < NTHR / 32; w++) s += sd[w];
            // + C0 (constant term of ln(1+u) poly), applied analytically
            out[0] = (float)(s * inv_n + 1.02e-5);
            g_count = 0;   // reset for next graph replay
        }
    }
}

extern "C" void kernel_launch(void* const* d_in, const int* in_sizes, int n_in,
                              void* d_out, int out_size) {
    const float* logits = (const float*)d_in[0];
    const int*   t32    = (const int*)d_in[1];   // int32 view of targets
    int nelem  = in_sizes[0];                    // B * (K-1)
    int total4 = nelem >> 2;

    coral_fused<<<NBLK, NTHR>>>((const float4*)logits, t32, total4,
                                (float*)d_out, 1.0 / (double)nelem);
}